// round 10
// baseline (speedup 1.0000x reference)
#include <cuda_runtime.h>
#include <cuda_bf16.h>
#include <math_constants.h>

#define EPSF 1e-7f
#define NMAX 8192
#define L2E  1.44269504f

// Interleaved per-box features: 3 float4 per box (single base pointer in loop).
//  [3i+0] = x1, y1, x2, y2
//  [3i+1] = area, 0.5*(x1+x2), 0.5*(y1+y2), (2/pi)*atan(w/(h+eps))
//  [3i+2] = conf, w, h, (spare)
__device__ float4 g_F[NMAX * 3];

__global__ void tgam_prep(const float* __restrict__ x, int n) {
    int i = blockIdx.x * blockDim.x + threadIdx.x;
    if (i >= n) return;
    float conf = x[i * 5 + 0];
    float x1 = x[i * 5 + 1];
    float y1 = x[i * 5 + 2];
    float x2 = x[i * 5 + 3];
    float y2 = x[i * 5 + 4];
    float w = x2 - x1;
    float h = y2 - y1;
    const float TWO_OVER_PI = 0.63661977236758134f;
    g_F[3 * i + 0] = make_float4(x1, y1, x2, y2);
    g_F[3 * i + 1] = make_float4(w * h, 0.5f * (x1 + x2), 0.5f * (y1 + y2),
                                 TWO_OVER_PI * atanf(__fdividef(w, h + EPSF)));
    g_F[3 * i + 2] = make_float4(conf, w, h, 0.0f);
}

__device__ __forceinline__ float safe_sigmoid(float xp) {
    float r = __fdividef(1.0f, 1.0f + __expf(-xp));
    return isfinite(r) ? r : 0.5f;
}

struct RowFeat {
    float x1, y1, x2, y2;   // box
    float biE;              // area + EPSF
    float sxh, syh;         // half center sums
    float atK;              // (2/pi)*atan
    float w, h;             // width, height
    float cil2;             // conf * log2(e)
    float conf;
};

__device__ __forceinline__ RowFeat load_row(int i) {
    RowFeat r;
    float4 A = g_F[3 * i + 0];
    float4 B = g_F[3 * i + 1];
    float4 C = g_F[3 * i + 2];
    r.x1 = A.x; r.y1 = A.y; r.x2 = A.z; r.y2 = A.w;
    r.biE = B.x + EPSF;
    r.sxh = B.y; r.syh = B.z; r.atK = B.w;
    r.conf = C.x; r.w = C.y; r.h = C.z;
    r.cil2 = C.x * L2E;
    return r;
}

// Per-pair score. Exact CIoU math with per-box constants prefolded:
//  - cw = (wi+wj) - iw_raw   (min+max identity)
//  - v  = da^2 with da in (2/pi)*atan units (K prefolded)
//  - rho2 = dx^2+dy^2 with half center sums (0.25 prefolded)
//  - v*alpha = v^2/den (one fused divide)
//  - p = ex2(ciou * cil2 * cj) (log2e prefolded)
__device__ __forceinline__ float score(
    const RowFeat& Ri, const float4 Fa, const float4 Fb, const float4 Fc)
{
    float iwr = fminf(Ri.x2, Fa.z) - fmaxf(Ri.x1, Fa.x);
    float ihr = fminf(Ri.y2, Fa.w) - fmaxf(Ri.y1, Fa.y);
    float iw = fmaxf(iwr, 0.0f);
    float ih = fmaxf(ihr, 0.0f);
    float inter = iw * ih;

    float uni = (Ri.biE + Fb.x) - inter;
    float iou = fminf(__fdividef(inter, uni), 1.0f);  // clamp: NaN-proof + more accurate

    float cw = (Ri.w + Fc.y) - iwr;
    float ch = (Ri.h + Fc.z) - ihr;
    float c2 = fmaf(cw, cw, fmaf(ch, ch, EPSF));

    float dx = Fb.y - Ri.sxh;
    float dy = Fb.z - Ri.syh;
    float rho2 = fmaf(dx, dx, dy * dy);
    float t2 = __fdividef(rho2, c2);

    float da = Fb.w - Ri.atK;
    float v  = da * da;
    float den = (v + (1.0f + EPSF)) - iou;  // >= EPSF since iou <= 1
    float t3 = __fdividef(v * v, den);      // = v * alpha

    float ciou = (iou - t2) - t3;

    float s2 = ciou * (Ri.cil2 * Fc.x);
    float p;
    asm("ex2.approx.f32 %0, %1;" : "=f"(p) : "f"(s2));
    return p;
}

#define R 4

// Four rows per CTA: j-features (3 x LDG.128) + loop overhead amortize over
// 4 score chains; 4 independent dependency chains per lane hide MUFU latency.
__global__ __launch_bounds__(256) void tgam_attn4(
    const float* __restrict__ gamma_p, float* __restrict__ out, int n)
{
    const int base = blockIdx.x * R;
    const int tid = threadIdx.x;

    RowFeat Rf[R];
#pragma unroll
    for (int r = 0; r < R; r++) {
        int i = base + r;
        if (i >= n) i = n - 1;   // duplicate loads on tail; writes guarded below
        Rf[r] = load_row(i);
    }

    float l[R];
    float b[R][5];
#pragma unroll
    for (int r = 0; r < R; r++) {
        l[r] = 0.f;
#pragma unroll
        for (int k = 0; k < 5; k++) b[r][k] = 0.f;
    }

#pragma unroll 2
    for (int j = tid; j < n; j += 256) {
        const float4 Fa = g_F[3 * j + 0];
        const float4 Fb = g_F[3 * j + 1];
        const float4 Fc = g_F[3 * j + 2];

#pragma unroll
        for (int r = 0; r < R; r++) {
            const float p = score(Rf[r], Fa, Fb, Fc);
            l[r]    += p;
            b[r][0] += p * Fc.x;
            b[r][1] += p * Fa.x;
            b[r][2] += p * Fa.y;
            b[r][3] += p * Fa.z;
            b[r][4] += p * Fa.w;
        }
    }

    // ---- block reduction of R*6 values ----
#pragma unroll
    for (int o = 16; o > 0; o >>= 1) {
#pragma unroll
        for (int r = 0; r < R; r++) {
            l[r] += __shfl_xor_sync(0xFFFFFFFFu, l[r], o);
#pragma unroll
            for (int k = 0; k < 5; k++)
                b[r][k] += __shfl_xor_sync(0xFFFFFFFFu, b[r][k], o);
        }
    }

    __shared__ float red[8][R * 6];
    const int warp = tid >> 5;
    const int lane = tid & 31;
    if (lane == 0) {
#pragma unroll
        for (int r = 0; r < R; r++) {
            red[warp][r * 6 + 0] = l[r];
#pragma unroll
            for (int k = 0; k < 5; k++) red[warp][r * 6 + 1 + k] = b[r][k];
        }
    }
    __syncthreads();

    // Threads 0..R-1 finalize one row each (parallel epilogue).
    if (tid < R) {
        const int i = base + tid;
        if (i < n) {
            float S[6];
#pragma unroll
            for (int k = 0; k < 6; k++) {
                float s = 0.f;
#pragma unroll
                for (int w = 0; w < 8; w++) s += red[w][tid * 6 + k];
                S[k] = s;
            }
            float g = gamma_p[0];
            if (!isfinite(g)) g = 0.0f;

            const RowFeat Ri = Rf[tid];
            const float inv = __fdividef(1.0f, S[0]);
            out[i * 5 + 0] = safe_sigmoid(Ri.conf * g + S[1] * inv);
            out[i * 5 + 1] = safe_sigmoid(Ri.x1   * g + S[2] * inv);
            out[i * 5 + 2] = safe_sigmoid(Ri.y1   * g + S[3] * inv);
            out[i * 5 + 3] = safe_sigmoid(Ri.x2   * g + S[4] * inv);
            out[i * 5 + 4] = safe_sigmoid(Ri.y2   * g + S[5] * inv);
        }
    }
}

extern "C" void kernel_launch(void* const* d_in, const int* in_sizes, int n_in,
                              void* d_out, int out_size) {
    // x = the big tensor, gamma = the 1-element one (ordering-proof).
    int xi = 0, gi = (n_in > 1) ? 1 : 0;
    if (n_in > 1 && in_sizes[1] > in_sizes[0]) { xi = 1; gi = 0; }

    const float* x     = (const float*)d_in[xi];
    const float* gamma = (const float*)d_in[gi];
    float* out         = (float*)d_out;

    // Bytes-vs-elements detection via the 1-element gamma.
    const int denom = (n_in > 1 && in_sizes[gi] == 4) ? 20 : 5;
    int n = in_sizes[xi] / denom;
    if (out_size > 0) {
        int n_out = out_size / denom;
        if (n_out > 0 && n_out < n) n = n_out;
    }
    if (n > NMAX) n = NMAX;
    if (n <= 0) n = 1;

    tgam_prep<<<(n + 127) / 128, 128>>>(x, n);
    tgam_attn4<<<(n + R - 1) / R, 256>>>(gamma, out, n);
}

// round 13
// speedup vs baseline: 1.0008x; 1.0008x over previous
#include <cuda_runtime.h>
#include <cuda_bf16.h>
#include <math_constants.h>

#define EPSF 1e-7f
#define NMAX 8192
#define L2E  1.44269504f

typedef unsigned long long u64;

// ---------- f32x2 packed helpers (sm_103a; IEEE .rn => bitwise == scalar) ----
__device__ __forceinline__ u64 pk2(float lo, float hi) {
    u64 r; asm("mov.b64 %0, {%1, %2};" : "=l"(r) : "f"(lo), "f"(hi)); return r;
}
__device__ __forceinline__ void upk2(u64 v, float& lo, float& hi) {
    asm("mov.b64 {%0, %1}, %2;" : "=f"(lo), "=f"(hi) : "l"(v));
}
__device__ __forceinline__ u64 add2(u64 a, u64 b) {
    u64 r; asm("add.rn.f32x2 %0, %1, %2;" : "=l"(r) : "l"(a), "l"(b)); return r;
}
__device__ __forceinline__ u64 mul2(u64 a, u64 b) {
    u64 r; asm("mul.rn.f32x2 %0, %1, %2;" : "=l"(r) : "l"(a), "l"(b)); return r;
}
__device__ __forceinline__ u64 fma2_(u64 a, u64 b, u64 c) {
    u64 r; asm("fma.rn.f32x2 %0, %1, %2, %3;" : "=l"(r) : "l"(a), "l"(b), "l"(c)); return r;
}
__device__ __forceinline__ float rcpf(float x) {
    float r; asm("rcp.approx.f32 %0, %1;" : "=f"(r) : "f"(x)); return r;
}
__device__ __forceinline__ float ex2f(float x) {
    float r; asm("ex2.approx.f32 %0, %1;" : "=f"(r) : "f"(x)); return r;
}

// ---------- Pair-interleaved features (even n path) ----------
// For j-pair p = (2p, 2p+1):  a = box 2p, b = box 2p+1
__device__ float4 g_Q0[NMAX / 2];  // x1a, x1b, y1a, y1b
__device__ float4 g_Q1[NMAX / 2];  // x2a, x2b, y2a, y2b
__device__ float4 g_Q2[NMAX / 2];  // cxa, cxb, cya, cyb   (half center sums)
__device__ float4 g_Q3[NMAX / 2];  // ata, atb, cfa, cfb   ((2/pi)*atan, conf)

// ---------- Legacy interleaved features (odd-n fallback) ----------
__device__ float4 g_F[NMAX * 3];

__global__ void tgam_prep_pairs(const float* __restrict__ x, int npair) {
    int p = blockIdx.x * blockDim.x + threadIdx.x;
    if (p >= npair) return;
    const float TWO_OVER_PI = 0.63661977236758134f;

    const float* xa = x + (2 * p) * 5;
    const float* xb = x + (2 * p + 1) * 5;
    float cfa = xa[0], x1a = xa[1], y1a = xa[2], x2a = xa[3], y2a = xa[4];
    float cfb = xb[0], x1b = xb[1], y1b = xb[2], x2b = xb[3], y2b = xb[4];
    float wa = x2a - x1a, ha = y2a - y1a;
    float wb = x2b - x1b, hb = y2b - y1b;

    g_Q0[p] = make_float4(x1a, x1b, y1a, y1b);
    g_Q1[p] = make_float4(x2a, x2b, y2a, y2b);
    g_Q2[p] = make_float4(0.5f * (x1a + x2a), 0.5f * (x1b + x2b),
                          0.5f * (y1a + y2a), 0.5f * (y1b + y2b));
    g_Q3[p] = make_float4(TWO_OVER_PI * atanf(__fdividef(wa, ha + EPSF)),
                          TWO_OVER_PI * atanf(__fdividef(wb, hb + EPSF)),
                          cfa, cfb);
}

__global__ void tgam_prep(const float* __restrict__ x, int n) {
    int i = blockIdx.x * blockDim.x + threadIdx.x;
    if (i >= n) return;
    float conf = x[i * 5 + 0];
    float x1 = x[i * 5 + 1];
    float y1 = x[i * 5 + 2];
    float x2 = x[i * 5 + 3];
    float y2 = x[i * 5 + 4];
    float w = x2 - x1;
    float h = y2 - y1;
    const float TWO_OVER_PI = 0.63661977236758134f;
    g_F[3 * i + 0] = make_float4(x1, y1, x2, y2);
    g_F[3 * i + 1] = make_float4(w * h, 0.5f * (x1 + x2), 0.5f * (y1 + y2),
                                 TWO_OVER_PI * atanf(__fdividef(w, h + EPSF)));
    g_F[3 * i + 2] = make_float4(conf, w, h, 0.0f);
}

__device__ __forceinline__ float safe_sigmoid(float xp) {
    float r = __fdividef(1.0f, 1.0f + __expf(-xp));
    return isfinite(r) ? r : 0.5f;
}

// ---------------- Packed-pair attention: 1 row/CTA, 128 threads ----------------
__global__ __launch_bounds__(128) void tgam_attn_p(
    const float* __restrict__ gamma_p, float* __restrict__ out, int n)
{
    const int i = blockIdx.x;
    const int tid = threadIdx.x;
    const int npair = n >> 1;

    // Row features (from pair arrays; broadcast loads, L1-resident).
    const int ip = i >> 1;
    const bool odd = (i & 1);
    const float4 r0 = g_Q0[ip], r1 = g_Q1[ip], r2 = g_Q2[ip], r3 = g_Q3[ip];
    const float Rx1 = odd ? r0.y : r0.x;
    const float Ry1 = odd ? r0.w : r0.z;
    const float Rx2 = odd ? r1.y : r1.x;
    const float Ry2 = odd ? r1.w : r1.z;
    const float Rcx = odd ? r2.y : r2.x;
    const float Rcy = odd ? r2.w : r2.z;
    const float Rat = odd ? r3.y : r3.x;
    const float Rcf = odd ? r3.w : r3.z;
    const float RwS = Rx2 - Rx1, RhS = Ry2 - Ry1;
    const float biE = RwS * RhS + EPSF;

    // Loop-invariant broadcast-packed row constants.
    const u64 biE2   = pk2(biE, biE);
    const u64 wR2    = pk2(RwS, RwS);
    const u64 hR2    = pk2(RhS, RhS);
    const u64 nsxh2  = pk2(-Rcx, -Rcx);
    const u64 nsyh2  = pk2(-Rcy, -Rcy);
    const u64 natK2  = pk2(-Rat, -Rat);
    const u64 cil22  = pk2(Rcf * L2E, Rcf * L2E);
    const u64 m1     = pk2(-1.0f, -1.0f);
    const u64 eps2   = pk2(EPSF, EPSF);
    const u64 onee2  = pk2(1.0f + EPSF, 1.0f + EPSF);

    u64 accL  = 0ull, accC  = 0ull;
    u64 accX1 = 0ull, accY1 = 0ull, accX2 = 0ull, accY2 = 0ull;

#pragma unroll 2
    for (int p = tid; p < npair; p += 128) {
        const float4 q0 = g_Q0[p];
        const float4 q1 = g_Q1[p];
        const float4 q2 = g_Q2[p];
        const float4 q3 = g_Q3[p];

        // --- scalar min/max chain (no packed FMNMX on sm_103a) ---
        const float iwra = fminf(Rx2, q1.x) - fmaxf(Rx1, q0.x);
        const float iwrb = fminf(Rx2, q1.y) - fmaxf(Rx1, q0.y);
        const float ihra = fminf(Ry2, q1.z) - fmaxf(Ry1, q0.z);
        const float ihrb = fminf(Ry2, q1.w) - fmaxf(Ry1, q0.w);
        const float intera = fmaxf(iwra, 0.0f) * fmaxf(ihra, 0.0f);
        const float interb = fmaxf(iwrb, 0.0f) * fmaxf(ihrb, 0.0f);

        // --- packed j-features (aligned reg pairs from LDG.128 -> free packs) ---
        const u64 x1_2 = pk2(q0.x, q0.y), y1_2 = pk2(q0.z, q0.w);
        const u64 x2_2 = pk2(q1.x, q1.y), y2_2 = pk2(q1.z, q1.w);
        const u64 w2    = fma2_(x1_2, m1, x2_2);   // xj2 - xj1
        const u64 h2    = fma2_(y1_2, m1, y2_2);
        const u64 area2 = mul2(w2, h2);
        const u64 inter2 = pk2(intera, interb);

        // iou = min(inter * rcp(union), 1)  (clamp: NaN-proof, see R5 post-mortem)
        const u64 uni2 = fma2_(inter2, m1, add2(biE2, area2));
        float ua, ub; upk2(uni2, ua, ub);
        const float ioua = fminf(intera * rcpf(ua), 1.0f);
        const float ioub = fminf(interb * rcpf(ub), 1.0f);
        const u64 iou2 = pk2(ioua, ioub);

        // enclosing box via min+max identity: cw = (wi+wj) - iwr
        const u64 iwr2 = pk2(iwra, iwrb);
        const u64 ihr2 = pk2(ihra, ihrb);
        const u64 cw2 = fma2_(iwr2, m1, add2(wR2, w2));
        const u64 ch2 = fma2_(ihr2, m1, add2(hR2, h2));
        const u64 c22 = fma2_(cw2, cw2, fma2_(ch2, ch2, eps2));
        float ca, cb; upk2(c22, ca, cb);
        const u64 rc2 = pk2(rcpf(ca), rcpf(cb));

        // center distance^2 (half sums; 0.25 prefolded)
        const u64 dx2 = add2(pk2(q2.x, q2.y), nsxh2);
        const u64 dy2 = add2(pk2(q2.z, q2.w), nsyh2);
        const u64 rho22 = fma2_(dx2, dx2, mul2(dy2, dy2));

        // aspect term: v = da^2 (K prefolded), v*alpha = v^2/den
        const u64 da2 = add2(pk2(q3.x, q3.y), natK2);
        const u64 v2  = mul2(da2, da2);
        const u64 den2 = fma2_(iou2, m1, add2(v2, onee2));  // >= eps since iou<=1
        float dna, dnb; upk2(den2, dna, dnb);
        const u64 rden2 = pk2(rcpf(dna), rcpf(dnb));
        const u64 t32 = mul2(mul2(v2, v2), rden2);
        const u64 t23 = fma2_(rho22, rc2, t32);            // rho2/c2 + v*alpha
        const u64 ciou2 = fma2_(t23, m1, iou2);

        // p = ex2(ciou * (ci*log2e) * cj)
        const u64 cf2 = pk2(q3.z, q3.w);
        const u64 s2 = mul2(ciou2, mul2(cf2, cil22));
        float sa, sb; upk2(s2, sa, sb);
        const u64 p2 = pk2(ex2f(sa), ex2f(sb));

        // packed accumulation (6 FFMA2/ADD2 for 2 pairs)
        accL  = add2(accL, p2);
        accC  = fma2_(p2, cf2,  accC);
        accX1 = fma2_(p2, x1_2, accX1);
        accY1 = fma2_(p2, y1_2, accY1);
        accX2 = fma2_(p2, x2_2, accX2);
        accY2 = fma2_(p2, y2_2, accY2);
    }

    // Collapse packed halves -> 6 scalars.
    float l, t, b0, b1, b2, b3, b4;
    { float a_, b_; upk2(accL,  a_, b_); l  = a_ + b_; }
    { float a_, b_; upk2(accC,  a_, b_); b0 = a_ + b_; }
    { float a_, b_; upk2(accX1, a_, b_); b1 = a_ + b_; }
    { float a_, b_; upk2(accY1, a_, b_); b2 = a_ + b_; }
    { float a_, b_; upk2(accX2, a_, b_); b3 = a_ + b_; }
    { float a_, b_; upk2(accY2, a_, b_); b4 = a_ + b_; }
    t = 0.0f; (void)t;

    // ---- block reduction (4 warps) ----
#pragma unroll
    for (int o = 16; o > 0; o >>= 1) {
        l  += __shfl_xor_sync(0xFFFFFFFFu, l,  o);
        b0 += __shfl_xor_sync(0xFFFFFFFFu, b0, o);
        b1 += __shfl_xor_sync(0xFFFFFFFFu, b1, o);
        b2 += __shfl_xor_sync(0xFFFFFFFFu, b2, o);
        b3 += __shfl_xor_sync(0xFFFFFFFFu, b3, o);
        b4 += __shfl_xor_sync(0xFFFFFFFFu, b4, o);
    }
    __shared__ float red[4][6];
    const int warp = tid >> 5, lane = tid & 31;
    if (lane == 0) {
        red[warp][0] = l;  red[warp][1] = b0; red[warp][2] = b1;
        red[warp][3] = b2; red[warp][4] = b3; red[warp][5] = b4;
    }
    __syncthreads();

    if (tid == 0) {
        float L = 0.f, A0 = 0.f, A1 = 0.f, A2 = 0.f, A3 = 0.f, A4 = 0.f;
#pragma unroll
        for (int w = 0; w < 4; w++) {
            L  += red[w][0]; A0 += red[w][1]; A1 += red[w][2];
            A2 += red[w][3]; A3 += red[w][4]; A4 += red[w][5];
        }
        const float inv = __fdividef(1.0f, L);
        float g = gamma_p[0];
        if (!isfinite(g)) g = 0.0f;

        out[i * 5 + 0] = safe_sigmoid(Rcf * g + A0 * inv);
        out[i * 5 + 1] = safe_sigmoid(Rx1 * g + A1 * inv);
        out[i * 5 + 2] = safe_sigmoid(Ry1 * g + A2 * inv);
        out[i * 5 + 3] = safe_sigmoid(Rx2 * g + A3 * inv);
        out[i * 5 + 4] = safe_sigmoid(Ry2 * g + A4 * inv);
    }
}

// ---------------- Fallback (round-9 scalar R=2 kernel) for odd n ----------------
struct RowFeat {
    float x1, y1, x2, y2, biE, sxh, syh, atK, w, h, cil2, conf;
};

__device__ __forceinline__ RowFeat load_row(int i) {
    RowFeat r;
    float4 A = g_F[3 * i + 0];
    float4 B = g_F[3 * i + 1];
    float4 C = g_F[3 * i + 2];
    r.x1 = A.x; r.y1 = A.y; r.x2 = A.z; r.y2 = A.w;
    r.biE = B.x + EPSF;
    r.sxh = B.y; r.syh = B.z; r.atK = B.w;
    r.conf = C.x; r.w = C.y; r.h = C.z;
    r.cil2 = C.x * L2E;
    return r;
}

__device__ __forceinline__ float score_fb(
    const RowFeat& Ri, const float4 Fa, const float4 Fb, const float4 Fc)
{
    float iwr = fminf(Ri.x2, Fa.z) - fmaxf(Ri.x1, Fa.x);
    float ihr = fminf(Ri.y2, Fa.w) - fmaxf(Ri.y1, Fa.y);
    float inter = fmaxf(iwr, 0.0f) * fmaxf(ihr, 0.0f);
    float uni = (Ri.biE + Fb.x) - inter;
    float iou = fminf(__fdividef(inter, uni), 1.0f);
    float cw = (Ri.w + Fc.y) - iwr;
    float ch = (Ri.h + Fc.z) - ihr;
    float c2 = fmaf(cw, cw, fmaf(ch, ch, EPSF));
    float dx = Fb.y - Ri.sxh;
    float dy = Fb.z - Ri.syh;
    float rho2 = fmaf(dx, dx, dy * dy);
    float da = Fb.w - Ri.atK;
    float v  = da * da;
    float den = (v + (1.0f + EPSF)) - iou;
    float t23 = fmaf(rho2, rcpf(c2), (v * v) * rcpf(den));
    float ciou = iou - t23;
    return ex2f(ciou * (Ri.cil2 * Fc.x));
}

__global__ __launch_bounds__(256) void tgam_attn_fb(
    const float* __restrict__ gamma_p, float* __restrict__ out, int n)
{
    const int i = blockIdx.x;
    const int tid = threadIdx.x;
    const RowFeat Ri = load_row(i);

    float l = 0.f, b0 = 0.f, b1 = 0.f, b2 = 0.f, b3 = 0.f, b4 = 0.f;
#pragma unroll 4
    for (int j = tid; j < n; j += 256) {
        const float4 Fa = g_F[3 * j + 0];
        const float4 Fb = g_F[3 * j + 1];
        const float4 Fc = g_F[3 * j + 2];
        const float p = score_fb(Ri, Fa, Fb, Fc);
        l += p; b0 += p * Fc.x;
        b1 += p * Fa.x; b2 += p * Fa.y; b3 += p * Fa.z; b4 += p * Fa.w;
    }
#pragma unroll
    for (int o = 16; o > 0; o >>= 1) {
        l  += __shfl_xor_sync(0xFFFFFFFFu, l,  o);
        b0 += __shfl_xor_sync(0xFFFFFFFFu, b0, o);
        b1 += __shfl_xor_sync(0xFFFFFFFFu, b1, o);
        b2 += __shfl_xor_sync(0xFFFFFFFFu, b2, o);
        b3 += __shfl_xor_sync(0xFFFFFFFFu, b3, o);
        b4 += __shfl_xor_sync(0xFFFFFFFFu, b4, o);
    }
    __shared__ float red[8][6];
    const int warp = tid >> 5, lane = tid & 31;
    if (lane == 0) {
        red[warp][0] = l;  red[warp][1] = b0; red[warp][2] = b1;
        red[warp][3] = b2; red[warp][4] = b3; red[warp][5] = b4;
    }
    __syncthreads();
    if (tid == 0) {
        float L = 0.f, A0 = 0.f, A1 = 0.f, A2 = 0.f, A3 = 0.f, A4 = 0.f;
#pragma unroll
        for (int w = 0; w < 8; w++) {
            L += red[w][0]; A0 += red[w][1]; A1 += red[w][2];
            A2 += red[w][3]; A3 += red[w][4]; A4 += red[w][5];
        }
        const float inv = __fdividef(1.0f, L);
        float g = gamma_p[0];
        if (!isfinite(g)) g = 0.0f;
        out[i * 5 + 0] = safe_sigmoid(Ri.conf * g + A0 * inv);
        out[i * 5 + 1] = safe_sigmoid(Ri.x1   * g + A1 * inv);
        out[i * 5 + 2] = safe_sigmoid(Ri.y1   * g + A2 * inv);
        out[i * 5 + 3] = safe_sigmoid(Ri.x2   * g + A3 * inv);
        out[i * 5 + 4] = safe_sigmoid(Ri.y2   * g + A4 * inv);
    }
}

extern "C" void kernel_launch(void* const* d_in, const int* in_sizes, int n_in,
                              void* d_out, int out_size) {
    // x = the big tensor, gamma = the 1-element one (ordering-proof).
    int xi = 0, gi = (n_in > 1) ? 1 : 0;
    if (n_in > 1 && in_sizes[1] > in_sizes[0]) { xi = 1; gi = 0; }

    const float* x     = (const float*)d_in[xi];
    const float* gamma = (const float*)d_in[gi];
    float* out         = (float*)d_out;

    // Bytes-vs-elements detection via the 1-element gamma.
    const int denom = (n_in > 1 && in_sizes[gi] == 4) ? 20 : 5;
    int n = in_sizes[xi] / denom;
    if (out_size > 0) {
        int n_out = out_size / denom;
        if (n_out > 0 && n_out < n) n = n_out;
    }
    if (n > NMAX) n = NMAX;
    if (n <= 0) n = 1;

    if ((n & 1) == 0) {
        const int npair = n >> 1;
        tgam_prep_pairs<<<(npair + 127) / 128, 128>>>(x, npair);
        tgam_attn_p<<<n, 128>>>(gamma, out, n);
    } else {
        tgam_prep<<<(n + 127) / 128, 128>>>(x, n);
        tgam_attn_fb<<<n, 256>>>(gamma, out, n);
    }
}